// round 5
// baseline (speedup 1.0000x reference)
#include <cuda_runtime.h>
#include <cstdint>

// LIF forward scan over 4 time steps.
// x: [STEP=4, N] fp32 (N = 64*128*32*32 = 8,388,608), out: same shape.
// Forward value of the surrogate spike is exactly the hard threshold (mem > 0.5).
// Pure streaming kernel: 128 MiB read + 128 MiB write -> HBM-bound.

static constexpr int STEP = 4;

__global__ __launch_bounds__(256)
void lif_fwd_kernel(const float4* __restrict__ x, float4* __restrict__ out, int n4) {
    int i = blockIdx.x * blockDim.x + threadIdx.x;
    if (i >= n4) return;

    // Issue all 4 time-step loads up front (independent addresses -> MLP=4).
    // Streaming hints: data is single-use in both directions.
    float4 x0 = __ldcs(&x[0 * (size_t)n4 + i]);
    float4 x1 = __ldcs(&x[1 * (size_t)n4 + i]);
    float4 x2 = __ldcs(&x[2 * (size_t)n4 + i]);
    float4 x3 = __ldcs(&x[3 * (size_t)n4 + i]);

    float4 mem = make_float4(0.f, 0.f, 0.f, 0.f);
    float4 s;

    // t = 0
    mem.x = fmaf(mem.x, 0.25f, x0.x); mem.y = fmaf(mem.y, 0.25f, x0.y);
    mem.z = fmaf(mem.z, 0.25f, x0.z); mem.w = fmaf(mem.w, 0.25f, x0.w);
    s.x = mem.x > 0.5f ? 1.f : 0.f;  s.y = mem.y > 0.5f ? 1.f : 0.f;
    s.z = mem.z > 0.5f ? 1.f : 0.f;  s.w = mem.w > 0.5f ? 1.f : 0.f;
    mem.x = s.x > 0.f ? 0.f : mem.x; mem.y = s.y > 0.f ? 0.f : mem.y;
    mem.z = s.z > 0.f ? 0.f : mem.z; mem.w = s.w > 0.f ? 0.f : mem.w;
    __stcs(&out[0 * (size_t)n4 + i], s);

    // t = 1
    mem.x = fmaf(mem.x, 0.25f, x1.x); mem.y = fmaf(mem.y, 0.25f, x1.y);
    mem.z = fmaf(mem.z, 0.25f, x1.z); mem.w = fmaf(mem.w, 0.25f, x1.w);
    s.x = mem.x > 0.5f ? 1.f : 0.f;  s.y = mem.y > 0.5f ? 1.f : 0.f;
    s.z = mem.z > 0.5f ? 1.f : 0.f;  s.w = mem.w > 0.5f ? 1.f : 0.f;
    mem.x = s.x > 0.f ? 0.f : mem.x; mem.y = s.y > 0.f ? 0.f : mem.y;
    mem.z = s.z > 0.f ? 0.f : mem.z; mem.w = s.w > 0.f ? 0.f : mem.w;
    __stcs(&out[1 * (size_t)n4 + i], s);

    // t = 2
    mem.x = fmaf(mem.x, 0.25f, x2.x); mem.y = fmaf(mem.y, 0.25f, x2.y);
    mem.z = fmaf(mem.z, 0.25f, x2.z); mem.w = fmaf(mem.w, 0.25f, x2.w);
    s.x = mem.x > 0.5f ? 1.f : 0.f;  s.y = mem.y > 0.5f ? 1.f : 0.f;
    s.z = mem.z > 0.5f ? 1.f : 0.f;  s.w = mem.w > 0.5f ? 1.f : 0.f;
    mem.x = s.x > 0.f ? 0.f : mem.x; mem.y = s.y > 0.f ? 0.f : mem.y;
    mem.z = s.z > 0.f ? 0.f : mem.z; mem.w = s.w > 0.f ? 0.f : mem.w;
    __stcs(&out[2 * (size_t)n4 + i], s);

    // t = 3 (no need to reset mem afterwards)
    mem.x = fmaf(mem.x, 0.25f, x3.x); mem.y = fmaf(mem.y, 0.25f, x3.y);
    mem.z = fmaf(mem.z, 0.25f, x3.z); mem.w = fmaf(mem.w, 0.25f, x3.w);
    s.x = mem.x > 0.5f ? 1.f : 0.f;  s.y = mem.y > 0.5f ? 1.f : 0.f;
    s.z = mem.z > 0.5f ? 1.f : 0.f;  s.w = mem.w > 0.5f ? 1.f : 0.f;
    __stcs(&out[3 * (size_t)n4 + i], s);
}

extern "C" void kernel_launch(void* const* d_in, const int* in_sizes, int n_in,
                              void* d_out, int out_size) {
    const float* x = (const float*)d_in[0];
    float* out = (float*)d_out;

    int total = in_sizes[0];          // STEP * N
    int n = total / STEP;             // elements per time step (8,388,608)
    int n4 = n / 4;                   // float4 count per step (2,097,152)

    int threads = 256;
    int blocks = (n4 + threads - 1) / threads;
    lif_fwd_kernel<<<blocks, threads>>>((const float4*)x, (float4*)out, n4);
}